// round 10
// baseline (speedup 1.0000x reference)
#include <cuda_runtime.h>
#include <cstdint>

// DAM softmax loss — persistent blocks, TMA (cp.async.bulk) 5-stage smem ring.
//   logits = S*costh, except target col: S*(ct - 0.15*exp(1-ct))
//   loss = mean_row( logsumexp(logits_row) - logits_row[target] )
// costh in [0,1) -> S*costh < 15 -> fixed max 15, single pass.
// Row = 40000 B = 5 chunks (4x8192 + 1x7232). Producer thread keeps a 5-deep
// ring full via mbarrier expect_tx; 512 threads consume from smem. In-flight
// bytes/SM ~160KB >> LDG's 32KB cap -> hides DRAM latency fully.

static constexpr int   B_ROWS  = 8192;
static constexpr int   C_COLS  = 10000;
static constexpr int   THREADS = 512;                  // 16 warps
static constexpr int   NUM_SMS = 148;
static constexpr int   BLOCKS_PER_SM = 4;
static constexpr int   GRID    = NUM_SMS * BLOCKS_PER_SM;   // 592
static constexpr int   STAGES  = 5;
static constexpr int   VEC_PER_CHUNK = 512;            // float4 per full chunk
static constexpr int   LAST_VEC = 2500 - 4 * VEC_PER_CHUNK; // 452
static constexpr float S_SCALE = 15.0f;
static constexpr float MARGIN_OVER_LAMDA = 0.3f / 2.0f;     // 0.15

__device__ double       g_acc  = 0.0;
__device__ unsigned int g_done = 0u;

__device__ __forceinline__ float ex2_approx(float x) {
    float r;
    asm("ex2.approx.f32 %0, %1;" : "=f"(r) : "f"(x));
    return r;
}

__device__ __forceinline__ uint32_t smem_u32(const void* p) {
    uint32_t a;
    asm("{ .reg .u64 t; cvta.to.shared.u64 t, %1; cvt.u32.u64 %0, t; }"
        : "=r"(a) : "l"(p));
    return a;
}

__device__ __forceinline__ void mbar_init(uint32_t addr, uint32_t cnt) {
    asm volatile("mbarrier.init.shared.b64 [%0], %1;" :: "r"(addr), "r"(cnt) : "memory");
}
__device__ __forceinline__ void mbar_expect_tx(uint32_t addr, uint32_t bytes) {
    asm volatile("mbarrier.arrive.expect_tx.shared.b64 _, [%0], %1;"
                 :: "r"(addr), "r"(bytes) : "memory");
}
__device__ __forceinline__ void mbar_arrive(uint32_t addr) {
    asm volatile("mbarrier.arrive.shared.b64 _, [%0];" :: "r"(addr) : "memory");
}
__device__ __forceinline__ void mbar_wait(uint32_t addr, uint32_t parity) {
    uint32_t done;
    asm volatile(
        "{\n\t.reg .pred p;\n\t"
        "mbarrier.try_wait.parity.acquire.cta.shared::cta.b64 p, [%1], %2;\n\t"
        "selp.b32 %0, 1, 0, p;\n\t}"
        : "=r"(done) : "r"(addr), "r"(parity) : "memory");
    if (!done) {
        asm volatile(
            "{\n\t.reg .pred P1;\n\t"
            "W_%=:\n\t"
            "mbarrier.try_wait.parity.acquire.cta.shared::cta.b64 P1, [%0], %1, 0x989680;\n\t"
            "@P1 bra.uni D_%=;\n\t"
            "bra.uni W_%=;\n\t"
            "D_%=:\n\t}"
            :: "r"(addr), "r"(parity) : "memory");
    }
}
__device__ __forceinline__ void bulk_g2s(uint32_t dst, const void* src,
                                         uint32_t bytes, uint32_t mbar) {
    asm volatile(
        "cp.async.bulk.shared::cluster.global.mbarrier::complete_tx::bytes "
        "[%0], [%1], %2, [%3];"
        :: "r"(dst), "l"(src), "r"(bytes), "r"(mbar) : "memory");
}

__global__ void __launch_bounds__(THREADS, BLOCKS_PER_SM)
dam_loss_tma_kernel(const float* __restrict__ costh,
                    const int* __restrict__ label,
                    float* __restrict__ out) {
    __shared__ __align__(128) float4 stage_buf[STAGES][VEC_PER_CHUNK]; // 40960 B
    __shared__ __align__(8) unsigned long long mb_full[STAGES], mb_empty[STAGES];
    __shared__ float warp_sums[2][THREADS / 32];
    __shared__ float sh_ct2[2];

    const int tid  = threadIdx.x;
    const int lane = tid & 31;

    const uint32_t full_a  = smem_u32(&mb_full[0]);
    const uint32_t empty_a = smem_u32(&mb_empty[0]);
    const uint32_t buf_a   = smem_u32(&stage_buf[0][0]);

    if (tid == 0) {
        #pragma unroll
        for (int s = 0; s < STAGES; s++) {
            mbar_init(full_a  + 8 * s, 1);              // producer expect_tx
            mbar_init(empty_a + 8 * s, THREADS / 32);   // one arrive per warp
        }
        asm volatile("fence.proxy.async.shared::cta;" ::: "memory");
    }
    __syncthreads();

    // exp(S*c - 15) = exp2( (S*log2e)*c - 15*log2e )
    const float L2E  = 1.4426950408889634f;
    const float SL2E = S_SCALE * L2E;
    const float BIAS = -S_SCALE * L2E;

    // Producer state (thread 0 only).
    int p_row = blockIdx.x;  // row being produced
    int p_it  = 0;           // produced-row iteration (phase source)
    int p_c   = 0;           // chunk within row
    int inflight = 0;        // issued-but-not-yet-consumed-by-thread0 (<= STAGES)

    int it = 0;              // consumer row iteration
    for (int row = blockIdx.x; row < B_ROWS; row += GRID, it++) {
        const int parity = it & 1;

        int t = __ldg(&label[row]);
        t = min(max(t, 0), C_COLS - 1);
        const int tv = t >> 2;
        const int tc = t & 3;

        float s0 = 0.0f, s1 = 0.0f, s2 = 0.0f, s3 = 0.0f;

        #pragma unroll
        for (int c = 0; c < STAGES; c++) {
            // Producer: top the ring up to STAGES chunks ahead.
            if (tid == 0) {
                while (inflight < STAGES && p_row < B_ROWS) {
                    mbar_wait(empty_a + 8 * p_c, (p_it & 1) ^ 1);
                    const uint32_t bytes =
                        (p_c == STAGES - 1) ? (uint32_t)(LAST_VEC * 16)
                                            : (uint32_t)(VEC_PER_CHUNK * 16);
                    mbar_expect_tx(full_a + 8 * p_c, bytes);
                    const float* src = costh + (size_t)p_row * C_COLS
                                     + (size_t)p_c * VEC_PER_CHUNK * 4;
                    bulk_g2s(buf_a + p_c * (VEC_PER_CHUNK * 16), src, bytes,
                             full_a + 8 * p_c);
                    inflight++;
                    if (++p_c == STAGES) { p_c = 0; p_it++; p_row += GRID; }
                }
            }

            // Consume chunk c (stage == c, phase == row parity).
            mbar_wait(full_a + 8 * c, parity);

            const int nv = (c == STAGES - 1) ? LAST_VEC : VEC_PER_CHUNK;
            if (tid < nv) {
                float4 v = stage_buf[c][tid];
                const int idx = c * VEC_PER_CHUNK + tid;
                if (idx == tv) {   // exactly one thread per row
                    float ct = (tc == 0) ? v.x : (tc == 1) ? v.y
                              : (tc == 2) ? v.z : v.w;
                    float ct2 = ct - MARGIN_OVER_LAMDA * expf(1.0f - ct);
                    if (tc == 0) v.x = ct2;
                    else if (tc == 1) v.y = ct2;
                    else if (tc == 2) v.z = ct2;
                    else v.w = ct2;
                    sh_ct2[parity] = ct2;
                }
                s0 += ex2_approx(fmaf(v.x, SL2E, BIAS));
                s1 += ex2_approx(fmaf(v.y, SL2E, BIAS));
                s2 += ex2_approx(fmaf(v.z, SL2E, BIAS));
                s3 += ex2_approx(fmaf(v.w, SL2E, BIAS));
            }
            __syncwarp();
            if (lane == 0) mbar_arrive(empty_a + 8 * c);
            if (tid == 0) inflight--;
        }

        // Block reduce for this row.
        float s = (s0 + s1) + (s2 + s3);
        #pragma unroll
        for (int off = 16; off; off >>= 1)
            s += __shfl_xor_sync(0xffffffffu, s, off);
        if (lane == 0) warp_sums[parity][tid >> 5] = s;
        __syncthreads();

        if (tid == 0) {
            float tot = 0.0f;
            #pragma unroll
            for (int w = 0; w < THREADS / 32; w++) tot += warp_sums[parity][w];
            const float ct2 = sh_ct2[parity];
            const float loss_row = 15.0f + logf(tot) - S_SCALE * ct2;
            atomicAdd(&g_acc, (double)loss_row);
        }
        // Parity double-buffering covers thread-0 lag; buffers of this parity
        // are rewritten only after the next same-parity row's consume, which
        // is gated by this row's __syncthreads for all warps.
    }

    if (tid == 0) {
        __threadfence();
        const unsigned ticket = atomicAdd(&g_done, 1u);
        if (ticket == (unsigned)(GRID - 1)) {
            out[0] = (float)(g_acc * (1.0 / (double)B_ROWS));
            g_acc  = 0.0;
            g_done = 0u;
            __threadfence();
        }
    }
}

extern "C" void kernel_launch(void* const* d_in, const int* in_sizes, int n_in,
                              void* d_out, int out_size) {
    const float* costh = (const float*)d_in[0];
    const int*   label = (const int*)d_in[1];
    float*       out   = (float*)d_out;

    dam_loss_tma_kernel<<<GRID, THREADS>>>(costh, label, out);
}